// round 8
// baseline (speedup 1.0000x reference)
#include <cuda_runtime.h>
#include <cuda_bf16.h>

#define K_DIM 1024
#define E_DIM 64
#define NVEC  (16 * 64 * 64)        // 65536 vectors
#define NPIX  (16 * 64 * 64 * 64)   // 4194304 output elements (vq part)
#define KC    128                   // codebook entries per shared-memory chunk
#define NCTA  (NVEC / 128)          // 512 CTAs, 128 threads, 1 vector/thread

__device__ double       d_loss_acc;   // zero-init; reset by last CTA each call
__device__ unsigned int d_ticket;     // zero-init; reset by last CTA each call

// ---- packed f32x2 helpers (sm_103a) ----
__device__ __forceinline__ void fma2(unsigned long long& d,
                                     unsigned long long a,
                                     unsigned long long b) {
    asm("fma.rn.f32x2 %0, %1, %2, %0;" : "+l"(d) : "l"(a), "l"(b));
}
__device__ __forceinline__ void add2(unsigned long long& d,
                                     unsigned long long a) {
    asm("add.rn.f32x2 %0, %0, %1;" : "+l"(d) : "l"(a));
}
__device__ __forceinline__ float2 unpack2(unsigned long long v) {
    float2 r;
    asm("mov.b64 {%0, %1}, %2;" : "=f"(r.x), "=f"(r.y) : "l"(v));
    return r;
}
__device__ __forceinline__ unsigned long long pack2(float lo, float hi) {
    unsigned long long v;
    asm("mov.b64 %0, {%1, %2};" : "=l"(v) : "f"(lo), "f"(hi));
    return v;
}

// Single fused kernel: chunked codebook in SMEM, per-chunk e2 computed in-CTA
// (same float4-sequential order as before -> bit-identical), T=1 vector/thread
// at 4 warps/SMSP to saturate the half-rate fma pipe, last-CTA loss finalize.
__global__ __launch_bounds__(128, 4)
void vq_kernel(const float* __restrict__ z,
               const float* __restrict__ cb,
               float* __restrict__ out_vq,
               float* __restrict__ out_loss,
               int has_loss) {
    __shared__ float sh_cb[KC * E_DIM];   // 32 KB
    __shared__ float sh_e2[KC];

    const int tid  = threadIdx.x;
    const int n    = blockIdx.x * 128 + tid;                  // this thread's vector
    const int base = (n >> 12) * (E_DIM * 4096) + (n & 4095); // z[b,c,h,w]=z[base+c*4096]

    // z row in registers as packed f32x2 (64 regs).
    unsigned long long zr[E_DIM / 2];
#pragma unroll
    for (int i = 0; i < E_DIM / 2; i++)
        zr[i] = pack2(z[base + (2 * i) * 4096], z[base + (2 * i + 1) * 4096]);

    // ||z||^2 fp32, sequential pair order (reference-matching rounding anchor).
    float z2 = 0.f;
#pragma unroll
    for (int i = 0; i < E_DIM / 2; i++) {
        float2 v = unpack2(zr[i]);
        z2 = __fadd_rn(z2, __fadd_rn(__fmul_rn(v.x, v.x), __fmul_rn(v.y, v.y)));
    }

    float best = 3.4e38f;
    int   bidx = 0;

    for (int k0 = 0; k0 < K_DIM; k0 += KC) {
        __syncthreads();
        // Cooperative chunk load: KC*64 floats = 2048 float4 / 128 threads
        const float4* src = reinterpret_cast<const float4*>(cb + k0 * E_DIM);
        float4* dst = reinterpret_cast<float4*>(sh_cb);
#pragma unroll
        for (int i = 0; i < (KC * E_DIM / 4) / 128; i++)
            dst[tid + i * 128] = src[tid + i * 128];
        __syncthreads();
        // e2 for row tid of this chunk: float4-sequential order (identical bits
        // to the previous standalone e2 kernel).
        {
            const float4* r = reinterpret_cast<const float4*>(sh_cb + tid * E_DIM);
            float s = 0.f;
#pragma unroll
            for (int i = 0; i < E_DIM / 4; i++) {
                float4 v = r[i];
                s += v.x * v.x + v.y * v.y + v.z * v.z + v.w * v.w;
            }
            sh_e2[tid] = s;
        }
        __syncthreads();

#pragma unroll 1
        for (int j = 0; j < KC; j += 2) {
            const ulonglong2* eA =
                reinterpret_cast<const ulonglong2*>(sh_cb + j * E_DIM);
            const ulonglong2* eB =
                reinterpret_cast<const ulonglong2*>(sh_cb + (j + 1) * E_DIM);
            // 8 independent chains (2 codes x 4 chains). Per-code tree is
            // bit-identical to the round-3/7 kernels.
            unsigned long long a0 = 0, a1 = 0, a2 = 0, a3 = 0;   // code j
            unsigned long long c0 = 0, c1 = 0, c2 = 0, c3 = 0;   // code j+1
#pragma unroll
            for (int i = 0; i < 8; i++) {          // 4 LDS.128 + 8 FFMA2 per step
                ulonglong2 xA0 = eA[2 * i];
                ulonglong2 xA1 = eA[2 * i + 1];
                ulonglong2 xB0 = eB[2 * i];
                ulonglong2 xB1 = eB[2 * i + 1];
                fma2(a0, zr[4 * i + 0], xA0.x);
                fma2(c0, zr[4 * i + 0], xB0.x);
                fma2(a1, zr[4 * i + 1], xA0.y);
                fma2(c1, zr[4 * i + 1], xB0.y);
                fma2(a2, zr[4 * i + 2], xA1.x);
                fma2(c2, zr[4 * i + 2], xB1.x);
                fma2(a3, zr[4 * i + 3], xA1.y);
                fma2(c3, zr[4 * i + 3], xB1.y);
            }
            add2(a0, a1); add2(a2, a3); add2(a0, a2);
            add2(c0, c1); add2(c2, c3); add2(c0, c2);
            float2 sA = unpack2(a0);
            float2 sB = unpack2(c0);
            float dotA = __fadd_rn(sA.x, sA.y);
            float dotB = __fadd_rn(sB.x, sB.y);
            // Reference fp32 rounding: (z2 + e2) - 2*dot (fma form, exact 2*dot).
            // Code j strictly before j+1: first-occurrence tie-break preserved.
            float dA = __fmaf_rn(-2.0f, dotA, __fadd_rn(z2, sh_e2[j]));
            if (dA < best) { best = dA; bidx = k0 + j; }
            float dB = __fmaf_rn(-2.0f, dotB, __fadd_rn(z2, sh_e2[j + 1]));
            if (dB < best) { best = dB; bidx = k0 + j + 1; }
        }
    }

    // Epilogue: gather winning row (L2-resident), write vq, accumulate loss.
    const float2* er = reinterpret_cast<const float2*>(cb + bidx * E_DIM);
    float local = 0.f;
#pragma unroll
    for (int i = 0; i < E_DIM / 2; i++) {
        float2 e  = __ldg(&er[i]);
        float2 zp = unpack2(zr[i]);
        float q0 = e.x - zp.x, q1 = e.y - zp.y;
        local += q0 * q0 + q1 * q1;
        out_vq[base + (2 * i)     * 4096] = e.x;
        out_vq[base + (2 * i + 1) * 4096] = e.y;
    }
#pragma unroll
    for (int o = 16; o; o >>= 1)
        local += __shfl_xor_sync(0xFFFFFFFFu, local, o);
    if ((tid & 31) == 0)
        atomicAdd(&d_loss_acc, (double)local);

    // Last-CTA finalize (self-resetting: deterministic across graph replays).
    __syncthreads();
    if (tid == 0) {
        __threadfence();
        unsigned int done = atomicAdd(&d_ticket, 1u);
        if (done == (unsigned int)(NCTA - 1)) {
            if (has_loss)
                *out_loss = (float)(1.25 * d_loss_acc / (double)NPIX);
            d_loss_acc = 0.0;
            d_ticket   = 0u;
            __threadfence();
        }
    }
}

extern "C" void kernel_launch(void* const* d_in, const int* in_sizes, int n_in,
                              void* d_out, int out_size) {
    // metadata order: z [16,64,64,64] fp32, codebook [1024,64] fp32.
    const float* z  = (const float*)d_in[0];
    const float* cb = (const float*)d_in[1];
    if (n_in >= 2 && in_sizes[0] == K_DIM * E_DIM && in_sizes[1] == NPIX) {
        const float* t = z; z = cb; cb = t;   // defensive: inputs swapped
    }

    float* out = (float*)d_out;
    int voff = out_size - NPIX;            // 1 if scalar loss precedes vq_out
    if (voff < 0) voff = 0;
    float* out_vq = out + voff;

    vq_kernel<<<NCTA, 128>>>(z, cb, out_vq, out, voff > 0 ? 1 : 0);
}

// round 9
// speedup vs baseline: 1.1085x; 1.1085x over previous
#include <cuda_runtime.h>
#include <cuda_bf16.h>

#define K_DIM 1024
#define E_DIM 64
#define NVEC  (16 * 64 * 64)        // 65536 vectors
#define NPIX  (16 * 64 * 64 * 64)   // 4194304 output elements (vq part)
#define KC    64                    // codebook entries per smem chunk
#define NCTA  (NVEC / 64)           // 1024 CTAs, 32 threads, 2 vectors/thread

__device__ double       d_loss_acc;   // zero-init; reset by last CTA each call
__device__ unsigned int d_ticket;     // zero-init; reset by last CTA each call

// ---- packed f32x2 helpers (sm_103a) ----
__device__ __forceinline__ void fma2(unsigned long long& d,
                                     unsigned long long a,
                                     unsigned long long b) {
    asm("fma.rn.f32x2 %0, %1, %2, %0;" : "+l"(d) : "l"(a), "l"(b));
}
__device__ __forceinline__ void add2(unsigned long long& d,
                                     unsigned long long a) {
    asm("add.rn.f32x2 %0, %0, %1;" : "+l"(d) : "l"(a));
}
__device__ __forceinline__ float2 unpack2(unsigned long long v) {
    float2 r;
    asm("mov.b64 {%0, %1}, %2;" : "=f"(r.x), "=f"(r.y) : "l"(v));
    return r;
}
__device__ __forceinline__ unsigned long long pack2(float lo, float hi) {
    unsigned long long v;
    asm("mov.b64 %0, {%1, %2};" : "=l"(v) : "f"(lo), "f"(hi));
    return v;
}

// 32-thread CTAs (1024 of them): fine-grained work-steal balance across 148 SMs,
// ~10 resident CTAs/SM (reg-capped) = 2.5 warps/SMSP. T=2 vectors/thread keeps
// L1 LDS-wavefront demand at half the fma-pipe floor. Arithmetic is bit-identical
// to the round-7 kernel (4-chain f32x2 dot tree, (z2+e2)-2*dot fp32 structure,
// in-chunk float4-sequential e2).
__global__ __launch_bounds__(32, 10)
void vq_kernel(const float* __restrict__ z,
               const float* __restrict__ cb,
               float* __restrict__ out_vq,
               float* __restrict__ out_loss,
               int has_loss) {
    __shared__ float sh_cb[KC * E_DIM];   // 16 KB
    __shared__ float sh_e2[KC];

    const int tid   = threadIdx.x;                 // 0..31
    const int n0    = blockIdx.x * 64 + tid;       // vectors n0, n0+32 (same b)
    const int base0 = (n0 >> 12) * (E_DIM * 4096) + (n0 & 4095);
    const int base1 = base0 + 32;

    // Both z rows in registers as packed f32x2.
    unsigned long long zr0[E_DIM / 2], zr1[E_DIM / 2];
#pragma unroll
    for (int i = 0; i < E_DIM / 2; i++) {
        zr0[i] = pack2(z[base0 + (2 * i) * 4096], z[base0 + (2 * i + 1) * 4096]);
        zr1[i] = pack2(z[base1 + (2 * i) * 4096], z[base1 + (2 * i + 1) * 4096]);
    }

    // ||z||^2 fp32, sequential pair order (reference-matching rounding anchor).
    float z20 = 0.f, z21 = 0.f;
#pragma unroll
    for (int i = 0; i < E_DIM / 2; i++) {
        float2 v0 = unpack2(zr0[i]);
        float2 v1 = unpack2(zr1[i]);
        z20 = __fadd_rn(z20, __fadd_rn(__fmul_rn(v0.x, v0.x), __fmul_rn(v0.y, v0.y)));
        z21 = __fadd_rn(z21, __fadd_rn(__fmul_rn(v1.x, v1.x), __fmul_rn(v1.y, v1.y)));
    }

    float best0 = 3.4e38f, best1 = 3.4e38f;
    int   bidx0 = 0,       bidx1 = 0;

    for (int k0 = 0; k0 < K_DIM; k0 += KC) {
        __syncthreads();
        // Cooperative chunk load: KC*64 floats = 1024 float4 / 32 threads
        const float4* src = reinterpret_cast<const float4*>(cb + k0 * E_DIM);
        float4* dst = reinterpret_cast<float4*>(sh_cb);
#pragma unroll
        for (int i = 0; i < (KC * E_DIM / 4) / 32; i++)
            dst[tid + i * 32] = src[tid + i * 32];
        __syncthreads();
        // e2 rows tid and tid+32: float4-sequential order (bit-identical).
#pragma unroll
        for (int rr = 0; rr < 2; rr++) {
            int r = tid + rr * 32;
            const float4* rp = reinterpret_cast<const float4*>(sh_cb + r * E_DIM);
            float s = 0.f;
#pragma unroll
            for (int i = 0; i < E_DIM / 4; i++) {
                float4 v = rp[i];
                s += v.x * v.x + v.y * v.y + v.z * v.z + v.w * v.w;
            }
            sh_e2[r] = s;
        }
        __syncthreads();

#pragma unroll 1
        for (int j = 0; j < KC; j += 2) {
            const ulonglong2* eA =
                reinterpret_cast<const ulonglong2*>(sh_cb + j * E_DIM);
            const ulonglong2* eB =
                reinterpret_cast<const ulonglong2*>(sh_cb + (j + 1) * E_DIM);
            // 16 independent chains (2 vec x 2 codes x 4 chains); per-(vec,code)
            // tree identical to rounds 3/7.
            unsigned long long a0 = 0, a1 = 0, a2 = 0, a3 = 0;   // vec0 x code j
            unsigned long long b0 = 0, b1 = 0, b2 = 0, b3 = 0;   // vec1 x code j
            unsigned long long c0 = 0, c1 = 0, c2 = 0, c3 = 0;   // vec0 x code j+1
            unsigned long long d0 = 0, d1 = 0, d2 = 0, d3 = 0;   // vec1 x code j+1
#pragma unroll
            for (int i = 0; i < 8; i++) {          // 4 LDS.128 + 16 FFMA2 per step
                ulonglong2 xA0 = eA[2 * i];
                ulonglong2 xA1 = eA[2 * i + 1];
                ulonglong2 xB0 = eB[2 * i];
                ulonglong2 xB1 = eB[2 * i + 1];
                fma2(a0, zr0[4 * i + 0], xA0.x);
                fma2(b0, zr1[4 * i + 0], xA0.x);
                fma2(c0, zr0[4 * i + 0], xB0.x);
                fma2(d0, zr1[4 * i + 0], xB0.x);
                fma2(a1, zr0[4 * i + 1], xA0.y);
                fma2(b1, zr1[4 * i + 1], xA0.y);
                fma2(c1, zr0[4 * i + 1], xB0.y);
                fma2(d1, zr1[4 * i + 1], xB0.y);
                fma2(a2, zr0[4 * i + 2], xA1.x);
                fma2(b2, zr1[4 * i + 2], xA1.x);
                fma2(c2, zr0[4 * i + 2], xB1.x);
                fma2(d2, zr1[4 * i + 2], xB1.x);
                fma2(a3, zr0[4 * i + 3], xA1.y);
                fma2(b3, zr1[4 * i + 3], xA1.y);
                fma2(c3, zr0[4 * i + 3], xB1.y);
                fma2(d3, zr1[4 * i + 3], xB1.y);
            }
            add2(a0, a1); add2(a2, a3); add2(a0, a2);
            add2(b0, b1); add2(b2, b3); add2(b0, b2);
            add2(c0, c1); add2(c2, c3); add2(c0, c2);
            add2(d0, d1); add2(d2, d3); add2(d0, d2);
            float2 sA0 = unpack2(a0), sA1 = unpack2(b0);
            float2 sB0 = unpack2(c0), sB1 = unpack2(d0);
            float dotA0 = __fadd_rn(sA0.x, sA0.y);
            float dotA1 = __fadd_rn(sA1.x, sA1.y);
            float dotB0 = __fadd_rn(sB0.x, sB0.y);
            float dotB1 = __fadd_rn(sB1.x, sB1.y);
            float e2A = sh_e2[j], e2B = sh_e2[j + 1];
            // Reference fp32 rounding: (z2 + e2) - 2*dot (fma form, exact 2*dot).
            // Code j strictly before j+1: first-occurrence tie-break preserved.
            float dA0 = __fmaf_rn(-2.0f, dotA0, __fadd_rn(z20, e2A));
            float dA1 = __fmaf_rn(-2.0f, dotA1, __fadd_rn(z21, e2A));
            if (dA0 < best0) { best0 = dA0; bidx0 = k0 + j; }
            if (dA1 < best1) { best1 = dA1; bidx1 = k0 + j; }
            float dB0 = __fmaf_rn(-2.0f, dotB0, __fadd_rn(z20, e2B));
            float dB1 = __fmaf_rn(-2.0f, dotB1, __fadd_rn(z21, e2B));
            if (dB0 < best0) { best0 = dB0; bidx0 = k0 + j + 1; }
            if (dB1 < best1) { best1 = dB1; bidx1 = k0 + j + 1; }
        }
    }

    // Epilogue: gather winning rows (L2-resident), write vq, accumulate loss.
    float local = 0.f;
    {
        const float2* er = reinterpret_cast<const float2*>(cb + bidx0 * E_DIM);
#pragma unroll
        for (int i = 0; i < E_DIM / 2; i++) {
            float2 e  = __ldg(&er[i]);
            float2 zp = unpack2(zr0[i]);
            float q0 = e.x - zp.x, q1 = e.y - zp.y;
            local += q0 * q0 + q1 * q1;
            out_vq[base0 + (2 * i)     * 4096] = e.x;
            out_vq[base0 + (2 * i + 1) * 4096] = e.y;
        }
    }
    {
        const float2* er = reinterpret_cast<const float2*>(cb + bidx1 * E_DIM);
#pragma unroll
        for (int i = 0; i < E_DIM / 2; i++) {
            float2 e  = __ldg(&er[i]);
            float2 zp = unpack2(zr1[i]);
            float q0 = e.x - zp.x, q1 = e.y - zp.y;
            local += q0 * q0 + q1 * q1;
            out_vq[base1 + (2 * i)     * 4096] = e.x;
            out_vq[base1 + (2 * i + 1) * 4096] = e.y;
        }
    }

    // warp reduce + one double atomic per CTA (CTA == 1 warp)
#pragma unroll
    for (int o = 16; o; o >>= 1)
        local += __shfl_xor_sync(0xFFFFFFFFu, local, o);
    if (tid == 0)
        atomicAdd(&d_loss_acc, (double)local);

    // Last-CTA finalize (self-resetting: deterministic across graph replays).
    if (tid == 0) {
        __threadfence();
        unsigned int done = atomicAdd(&d_ticket, 1u);
        if (done == (unsigned int)(NCTA - 1)) {
            if (has_loss)
                *out_loss = (float)(1.25 * d_loss_acc / (double)NPIX);
            d_loss_acc = 0.0;
            d_ticket   = 0u;
            __threadfence();
        }
    }
}

extern "C" void kernel_launch(void* const* d_in, const int* in_sizes, int n_in,
                              void* d_out, int out_size) {
    // metadata order: z [16,64,64,64] fp32, codebook [1024,64] fp32.
    const float* z  = (const float*)d_in[0];
    const float* cb = (const float*)d_in[1];
    if (n_in >= 2 && in_sizes[0] == K_DIM * E_DIM && in_sizes[1] == NPIX) {
        const float* t = z; z = cb; cb = t;   // defensive: inputs swapped
    }

    float* out = (float*)d_out;
    int voff = out_size - NPIX;            // 1 if scalar loss precedes vq_out
    if (voff < 0) voff = 0;
    float* out_vq = out + voff;

    vq_kernel<<<NCTA, 32>>>(z, cb, out_vq, out, voff > 0 ? 1 : 0);
}